// round 1
// baseline (speedup 1.0000x reference)
#include <cuda_runtime.h>
#include <math.h>

#define FEAT_DIM 360
#define MAXB     32
#define NT       256
#define TILE     32

__device__ float g_feat[MAXB * FEAT_DIM];

__device__ __forceinline__ float lrelu(float v) { return v >= 0.0f ? v : 0.2f * v; }

// ---------------- feature kernel: mean(thumb) @ Wm + bm ----------------
__global__ void feat_kernel(const float* __restrict__ thumb,
                            const float* __restrict__ Wm,
                            const float* __restrict__ bm, int HW) {
    int b = blockIdx.x;
    int tid = threadIdx.x;
    __shared__ float red[3][NT];
    const float* base = thumb + (size_t)b * 3 * HW;
    float s0 = 0.f, s1 = 0.f, s2 = 0.f;
    for (int i = tid; i < HW; i += NT) {
        s0 += base[i];
        s1 += base[HW + i];
        s2 += base[2 * HW + i];
    }
    red[0][tid] = s0; red[1][tid] = s1; red[2][tid] = s2;
    __syncthreads();
    for (int off = NT / 2; off > 0; off >>= 1) {
        if (tid < off) {
            red[0][tid] += red[0][tid + off];
            red[1][tid] += red[1][tid + off];
            red[2][tid] += red[2][tid + off];
        }
        __syncthreads();
    }
    float inv = 1.0f / (float)HW;
    float m0 = red[0][0] * inv, m1 = red[1][0] * inv, m2 = red[2][0] * inv;
    for (int j = tid; j < FEAT_DIM; j += NT) {
        g_feat[b * FEAT_DIM + j] =
            m0 * Wm[j] + m1 * Wm[FEAT_DIM + j] + m2 * Wm[2 * FEAT_DIM + j] + bm[j];
    }
}

// ---------------- fused conv-stack + attention ----------------
// One 3x3 conv layer, src (S x S x 3) -> dst (D x D x 3), D = S - 2.
// Weights hoisted to registers (uniform per CTA) so inner loop is LDS+FFMA only.
template <int S, int D>
__device__ __forceinline__ void conv3_step(const float* __restrict__ src,
                                           float* __restrict__ dst,
                                           const float* __restrict__ sFeat,
                                           int fbase, int tid) {
    float w[84];
#pragma unroll
    for (int j = 0; j < 84; j++) w[j] = sFeat[fbase + j];
    for (int p = tid; p < D * D; p += NT) {
        int y = p / D, x = p - y * D;
        float a0 = w[81], a1 = w[82], a2 = w[83];
#pragma unroll
        for (int ic = 0; ic < 3; ic++) {
            const float* s = src + (ic * S + y) * S + x;
#pragma unroll
            for (int ky = 0; ky < 3; ky++) {
#pragma unroll
                for (int kx = 0; kx < 3; kx++) {
                    float v = s[ky * S + kx];
                    a0 = fmaf(w[     ic * 9 + ky * 3 + kx], v, a0);
                    a1 = fmaf(w[27 + ic * 9 + ky * 3 + kx], v, a1);
                    a2 = fmaf(w[54 + ic * 9 + ky * 3 + kx], v, a2);
                }
            }
        }
        dst[p]             = lrelu(a0);
        dst[D * D + p]     = lrelu(a1);
        dst[2 * D * D + p] = lrelu(a2);
    }
}

__global__ __launch_bounds__(NT) void conv_att_kernel(const float* __restrict__ xin,
                                                      float* __restrict__ out,
                                                      int H, int W) {
    __shared__ float sFeat[FEAT_DIM];
    __shared__ float bufA[3 * 38 * 38];  // input, then reused as L2 (34x34)
    __shared__ float bufB[3 * 36 * 36];  // L1

    int b  = blockIdx.z;
    int x0 = blockIdx.x * TILE;
    int y0 = blockIdx.y * TILE;
    int tid = threadIdx.x;

    for (int j = tid; j < FEAT_DIM; j += NT) sFeat[j] = g_feat[b * FEAT_DIM + j];

    // load input tile with halo 3 (zero-padded at image borders)
    const float* xb = xin + (size_t)b * 3 * H * W;
    for (int i = tid; i < 3 * 38 * 38; i += NT) {
        int c = i / (38 * 38);
        int r = i - c * (38 * 38);
        int y = r / 38, xx = r - y * 38;
        int gy = y0 - 3 + y, gx = x0 - 3 + xx;
        float v = 0.0f;
        if (gy >= 0 && gy < H && gx >= 0 && gx < W)
            v = __ldg(&xb[((size_t)c * H + gy) * W + gx]);
        bufA[i] = v;
    }
    __syncthreads();

    // layer 1: bufA(38) -> bufB(36)
    conv3_step<38, 36>(bufA, bufB, sFeat, 0, tid);

    // stash residual (center of input) before bufA is reused as L2
    float res[4][3];
#pragma unroll
    for (int k = 0; k < 4; k++) {
        int p = tid + k * NT;
        int y = p >> 5, x = p & 31;
#pragma unroll
        for (int c = 0; c < 3; c++)
            res[k][c] = bufA[(c * 38 + (3 + y)) * 38 + (3 + x)];
    }
    __syncthreads();

    // layer 2: bufB(36) -> bufA(34)
    conv3_step<36, 34>(bufB, bufA, sFeat, 84, tid);
    __syncthreads();

    // layer 3: bufA(34) -> registers (exactly 4 pixels/thread of 32x32 tile)
    float cur[4][3];
    {
        float w[84];
#pragma unroll
        for (int j = 0; j < 84; j++) w[j] = sFeat[168 + j];
#pragma unroll
        for (int k = 0; k < 4; k++) {
            int p = tid + k * NT;
            int y = p >> 5, x = p & 31;
            float a0 = w[81], a1 = w[82], a2 = w[83];
#pragma unroll
            for (int ic = 0; ic < 3; ic++) {
                const float* s = bufA + (ic * 34 + y) * 34 + x;
#pragma unroll
                for (int ky = 0; ky < 3; ky++) {
#pragma unroll
                    for (int kx = 0; kx < 3; kx++) {
                        float v = s[ky * 34 + kx];
                        a0 = fmaf(w[     ic * 9 + ky * 3 + kx], v, a0);
                        a1 = fmaf(w[27 + ic * 9 + ky * 3 + kx], v, a1);
                        a2 = fmaf(w[54 + ic * 9 + ky * 3 + kx], v, a2);
                    }
                }
            }
            cur[k][0] = lrelu(a0); cur[k][1] = lrelu(a1); cur[k][2] = lrelu(a2);
        }
    }

    // 5x conv1x1 (per-pixel, in registers) + residual
    float w1[60];
#pragma unroll
    for (int j = 0; j < 60; j++) w1[j] = sFeat[252 + j];
#pragma unroll
    for (int k = 0; k < 4; k++) {
        float c0 = cur[k][0], c1 = cur[k][1], c2 = cur[k][2];
#pragma unroll
        for (int l = 0; l < 5; l++) {
            const float* wl = w1 + l * 12;
            float n0 = fmaf(wl[0], c0, fmaf(wl[1], c1, fmaf(wl[2], c2, wl[9])));
            float n1 = fmaf(wl[3], c0, fmaf(wl[4], c1, fmaf(wl[5], c2, wl[10])));
            float n2 = fmaf(wl[6], c0, fmaf(wl[7], c1, fmaf(wl[8], c2, wl[11])));
            c0 = lrelu(n0); c1 = lrelu(n1); c2 = lrelu(n2);
        }
        cur[k][0] = res[k][0] + c0;
        cur[k][1] = res[k][1] + c1;
        cur[k][2] = res[k][2] + c2;
    }

    // polynomial attention + store
    float invH = 1.0f / (float)H, invW = 1.0f / (float)W;
#pragma unroll
    for (int k = 0; k < 4; k++) {
        int p = tid + k * NT;
        int y = p >> 5, x = p & 31;
        int gy = y0 + y, gx = x0 + x;
        float hv = (float)gy * invH, wv = (float)gx * invW;
#pragma unroll
        for (int c = 0; c < 3; c++) {
            float v = cur[k][c];
            float att = 1.0f;
#pragma unroll
            for (int i = 0; i < 4; i++) {
                const float* f = sFeat + 312 + c * 16 + i * 4;
                att *= fmaf(f[0], hv, fmaf(f[1], wv, fmaf(f[2], v, f[3])));
            }
            out[((size_t)(b * 3 + c) * H + gy) * W + gx] = v * (1.0f + att);
        }
    }
}

// ---------------- launch ----------------
extern "C" void kernel_launch(void* const* d_in, const int* in_sizes, int n_in,
                              void* d_out, int out_size) {
    const float* x     = (const float*)d_in[0];
    const float* thumb = (const float*)d_in[1];
    const float* Wm    = (const float*)d_in[2];
    const float* bm    = (const float*)d_in[3];
    float* out = (float*)d_out;

    // thumb is (B,3,64,64); main is (B,3,H,H)
    int Ht = 64;
    int B  = in_sizes[1] / (3 * Ht * Ht);
    if (B < 1) B = 1;
    if (B > MAXB) B = MAXB;
    int hw = in_sizes[0] / (3 * B);
    int Hm = (int)(sqrt((double)hw) + 0.5);

    feat_kernel<<<B, NT>>>(thumb, Wm, bm, Ht * Ht);

    dim3 gMain(Hm / TILE, Hm / TILE, B);
    conv_att_kernel<<<gMain, NT>>>(x, out, Hm, Hm);

    dim3 gThumb(Ht / TILE, Ht / TILE, B);
    conv_att_kernel<<<gThumb, NT>>>(thumb, out + (size_t)B * 3 * Hm * Hm, Ht, Ht);
}

// round 2
// speedup vs baseline: 1.1377x; 1.1377x over previous
#include <cuda_runtime.h>
#include <math.h>

typedef unsigned long long ull;

#define FEAT_DIM 360
#define MAXB     32
#define NT       256
#define TILE     32

__device__ float g_mean[MAXB * 3];
__device__ float g_feat[MAXB * FEAT_DIM];

// ---------------- packed f32x2 helpers ----------------
__device__ __forceinline__ ull pack2(float lo, float hi) {
    ull r; asm("mov.b64 %0, {%1, %2};" : "=l"(r) : "f"(lo), "f"(hi)); return r;
}
__device__ __forceinline__ void unpack2(ull v, float& lo, float& hi) {
    asm("mov.b64 {%0, %1}, %2;" : "=f"(lo), "=f"(hi) : "l"(v));
}
__device__ __forceinline__ ull fma2(ull a, ull b, ull c) {
    ull r; asm("fma.rn.f32x2 %0, %1, %2, %3;" : "=l"(r) : "l"(a), "l"(b), "l"(c)); return r;
}
__device__ __forceinline__ ull mul2(ull a, ull b) {
    ull r; asm("mul.rn.f32x2 %0, %1, %2;" : "=l"(r) : "l"(a), "l"(b)); return r;
}
__device__ __forceinline__ ull add2(ull a, ull b) {
    ull r; asm("add.rn.f32x2 %0, %1, %2;" : "=l"(r) : "l"(a), "l"(b)); return r;
}

#define C06P 0x3F19999A3F19999AULL   // (0.6f, 0.6f)
#define C04P 0x3ECCCCCD3ECCCCCDULL   // (0.4f, 0.4f)
#define ONE2 0x3F8000003F800000ULL   // (1.0f, 1.0f)

// lrelu(v) = 0.6*v + 0.4*|v|  (== v for v>=0, 0.2v for v<0), branch-free packed
__device__ __forceinline__ ull lrelu2(ull v) {
    ull a = v & 0x7FFFFFFF7FFFFFFFULL;
    return fma2(a, (ull)C04P, mul2(v, (ull)C06P));
}

// ---------------- stage 1: per-channel mean ----------------
__global__ void mean_kernel(const float* __restrict__ thumb, int HW) {
    int b = blockIdx.x, c = blockIdx.y;
    int tid = threadIdx.x;
    const float4* p = (const float4*)(thumb + (size_t)(b * 3 + c) * HW);
    int n4 = HW / 4;
    float s = 0.0f;
    for (int i = tid; i < n4; i += NT) {
        float4 v = p[i];
        s += (v.x + v.y) + (v.z + v.w);
    }
    __shared__ float red[NT / 32];
    #pragma unroll
    for (int o = 16; o > 0; o >>= 1) s += __shfl_down_sync(0xffffffffu, s, o);
    if ((tid & 31) == 0) red[tid >> 5] = s;
    __syncthreads();
    if (tid < NT / 32) {
        s = red[tid];
        #pragma unroll
        for (int o = NT / 64; o > 0; o >>= 1) s += __shfl_down_sync(0xffu, s, o);
        if (tid == 0) g_mean[b * 3 + c] = s / (float)HW;
    }
}

// ---------------- stage 2: feature GEMV ----------------
__global__ void gemv_kernel(const float* __restrict__ Wm, const float* __restrict__ bm) {
    int b = blockIdx.x;
    int j = threadIdx.x;
    if (j < FEAT_DIM) {
        float m0 = g_mean[b * 3], m1 = g_mean[b * 3 + 1], m2 = g_mean[b * 3 + 2];
        g_feat[b * FEAT_DIM + j] =
            m0 * Wm[j] + m1 * Wm[FEAT_DIM + j] + m2 * Wm[2 * FEAT_DIM + j] + bm[j];
    }
}

// ---------------- one 3x3 conv layer on pixel pairs ----------------
// src (S x S x 3) -> dst (D x D x 3), D = S - 2. Each work item = 2 adjacent pixels.
// wPack: 84 pre-splatted (w,w) pairs for this layer.
template <int S, int D, int SLOTS, bool STORE>
__device__ __forceinline__ void conv3_pairs(const float* __restrict__ src,
                                            float* __restrict__ dst,
                                            const ull* __restrict__ wPack,
                                            int tid, ull outReg[][3]) {
    constexpr int PW = D / 2;
    constexpr int NP = D * PW;
    ull acc[SLOTS][3];
    #pragma unroll
    for (int oc = 0; oc < 3; oc++) {
        ull bb = wPack[81 + oc];
        #pragma unroll
        for (int k = 0; k < SLOTS; k++) acc[k][oc] = bb;
    }
    #pragma unroll
    for (int ic = 0; ic < 3; ic++) {
        ull w[9][3];
        #pragma unroll
        for (int t = 0; t < 9; t++)
            #pragma unroll
            for (int oc = 0; oc < 3; oc++)
                w[t][oc] = wPack[oc * 27 + ic * 9 + t];
        #pragma unroll
        for (int k = 0; k < SLOTS; k++) {
            int p = tid + k * NT;
            if (p < NP) {
                int y = p / PW, x = (p - y * PW) * 2;
                const float* s = src + (ic * S + y) * S + x;
                #pragma unroll
                for (int ky = 0; ky < 3; ky++) {
                    float2 s01 = *(const float2*)(s + ky * S);
                    float2 s23 = *(const float2*)(s + ky * S + 2);
                    ull v0 = pack2(s01.x, s01.y);
                    ull v1 = pack2(s01.y, s23.x);
                    ull v2 = pack2(s23.x, s23.y);
                    #pragma unroll
                    for (int oc = 0; oc < 3; oc++) {
                        acc[k][oc] = fma2(w[ky * 3 + 0][oc], v0, acc[k][oc]);
                        acc[k][oc] = fma2(w[ky * 3 + 1][oc], v1, acc[k][oc]);
                        acc[k][oc] = fma2(w[ky * 3 + 2][oc], v2, acc[k][oc]);
                    }
                }
            }
        }
    }
    #pragma unroll
    for (int k = 0; k < SLOTS; k++) {
        int p = tid + k * NT;
        if (p < NP) {
            int y = p / PW, x = (p - y * PW) * 2;
            #pragma unroll
            for (int oc = 0; oc < 3; oc++) {
                ull r = lrelu2(acc[k][oc]);
                if (STORE) *(ull*)(dst + oc * D * D + y * D + x) = r;
                else       outReg[k][oc] = r;
            }
        }
    }
}

// ---------------- fused conv stack + attention (main + thumb merged) ----------------
__global__ __launch_bounds__(NT, 2) void conv_att_kernel(
    const float* __restrict__ xMain, const float* __restrict__ xThumb,
    float* __restrict__ outAll, int Hm, int B, int tRowM) {
    __shared__ __align__(16) float bufA[3 * 38 * 38];
    __shared__ __align__(16) float bufB[3 * 36 * 36];
    __shared__ ull sPack[FEAT_DIM];

    int mainTotal = B * tRowM * tRowM;
    int bid = blockIdx.x;
    const float* src; float* dst;
    int H, tRow, b, tile;
    if (bid < mainTotal) {
        int per = tRowM * tRowM;
        b = bid / per; tile = bid - b * per;
        H = Hm; tRow = tRowM;
        src = xMain + (size_t)b * 3 * H * H;
        dst = outAll + (size_t)b * 3 * H * H;
    } else {
        int r = bid - mainTotal;
        b = r >> 2; tile = r & 3;
        H = 64; tRow = 2;
        src = xThumb + (size_t)b * 3 * 64 * 64;
        dst = outAll + (size_t)B * 3 * Hm * Hm + (size_t)b * 3 * 64 * 64;
    }
    int ty = tile / tRow, tx = tile - ty * tRow;
    int y0 = ty * TILE, x0 = tx * TILE;
    int tid = threadIdx.x;

    // splat features into packed SMEM table
    for (int j = tid; j < FEAT_DIM; j += NT) {
        float f = g_feat[b * FEAT_DIM + j];
        sPack[j] = pack2(f, f);
    }

    // load input tile with halo 3 (zero-padded at borders)
    for (int i = tid; i < 3 * 38 * 38; i += NT) {
        int c = i / (38 * 38);
        int r = i - c * (38 * 38);
        int y = r / 38, xx = r - y * 38;
        int gy = y0 - 3 + y, gx = x0 - 3 + xx;
        float v = 0.0f;
        if (gy >= 0 && gy < H && gx >= 0 && gx < H)
            v = __ldg(&src[((size_t)c * H + gy) * H + gx]);
        bufA[i] = v;
    }
    __syncthreads();

    // L1: bufA(38) -> bufB(36)
    conv3_pairs<38, 36, 3, true>(bufA, bufB, sPack, tid, (ull(*)[3])nullptr);

    // stash residual pairs (input tile center) before bufA is reused
    ull resP[2][3];
    #pragma unroll
    for (int k = 0; k < 2; k++) {
        int p = tid + k * NT;
        int y = p >> 4, x = (p & 15) * 2;
        #pragma unroll
        for (int oc = 0; oc < 3; oc++) {
            const float* q = &bufA[(oc * 38 + 3 + y) * 38 + 3 + x];
            resP[k][oc] = pack2(q[0], q[1]);
        }
    }
    __syncthreads();

    // L2: bufB(36) -> bufA(34)
    conv3_pairs<36, 34, 3, true>(bufB, bufA, sPack + 84, tid, (ull(*)[3])nullptr);
    __syncthreads();

    // L3: bufA(34) -> registers (2 pair-slots/thread, exactly 32x32 tile)
    ull cur[2][3];
    conv3_pairs<34, 32, 2, false>(bufA, (float*)nullptr, sPack + 168, tid, cur);

    // 5x conv1x1 (packed, in registers)
    #pragma unroll
    for (int l = 0; l < 5; l++) {
        const ull* wl = sPack + 252 + l * 12;
        ull W0 = wl[0], W1 = wl[1], W2 = wl[2];
        ull W3 = wl[3], W4 = wl[4], W5 = wl[5];
        ull W6 = wl[6], W7 = wl[7], W8 = wl[8];
        ull B0 = wl[9], B1 = wl[10], B2 = wl[11];
        #pragma unroll
        for (int k = 0; k < 2; k++) {
            ull c0 = cur[k][0], c1 = cur[k][1], c2 = cur[k][2];
            ull n0 = fma2(W0, c0, fma2(W1, c1, fma2(W2, c2, B0)));
            ull n1 = fma2(W3, c0, fma2(W4, c1, fma2(W5, c2, B1)));
            ull n2 = fma2(W6, c0, fma2(W7, c1, fma2(W8, c2, B2)));
            cur[k][0] = lrelu2(n0);
            cur[k][1] = lrelu2(n1);
            cur[k][2] = lrelu2(n2);
        }
    }
    // residual add
    #pragma unroll
    for (int k = 0; k < 2; k++)
        #pragma unroll
        for (int oc = 0; oc < 3; oc++)
            cur[k][oc] = add2(resP[k][oc], cur[k][oc]);

    // polynomial attention + store (packed, 2 pixels per store)
    float invH = 1.0f / (float)H;
    #pragma unroll
    for (int k = 0; k < 2; k++) {
        int p = tid + k * NT;
        int y = p >> 4, x = (p & 15) * 2;
        int gy = y0 + y, gx = x0 + x;
        float hv = (float)gy * invH;
        ull hP = pack2(hv, hv);
        ull wP = pack2((float)gx * invH, (float)(gx + 1) * invH);
        #pragma unroll
        for (int oc = 0; oc < 3; oc++) {
            ull v = cur[k][oc];
            ull att = (ull)ONE2;
            #pragma unroll
            for (int i = 0; i < 4; i++) {
                const ull* f = sPack + 312 + oc * 16 + i * 4;
                ull t = fma2(f[0], hP, fma2(f[1], wP, fma2(f[2], v, f[3])));
                att = mul2(att, t);
            }
            ull r = mul2(v, add2((ull)ONE2, att));
            *(ull*)&dst[((size_t)oc * H + gy) * H + gx] = r;
        }
    }
}

// ---------------- launch ----------------
extern "C" void kernel_launch(void* const* d_in, const int* in_sizes, int n_in,
                              void* d_out, int out_size) {
    const float* x     = (const float*)d_in[0];
    const float* thumb = (const float*)d_in[1];
    const float* Wm    = (const float*)d_in[2];
    const float* bm    = (const float*)d_in[3];
    float* out = (float*)d_out;

    int Ht = 64;
    int B  = in_sizes[1] / (3 * Ht * Ht);
    if (B < 1) B = 1;
    if (B > MAXB) B = MAXB;
    int hw = in_sizes[0] / (3 * B);
    int Hm = (int)(sqrt((double)hw) + 0.5);

    mean_kernel<<<dim3(B, 3), NT>>>(thumb, Ht * Ht);
    gemv_kernel<<<B, 384>>>(Wm, bm);

    int tRowM = Hm / TILE;
    int total = B * tRowM * tRowM + B * 4;  // main tiles + thumb tiles
    conv_att_kernel<<<total, NT>>>(x, thumb, out, Hm, B, tRowM);
}

// round 3
// speedup vs baseline: 1.2733x; 1.1192x over previous
#include <cuda_runtime.h>
#include <math.h>

typedef unsigned long long ull;

#define FEAT_DIM 360
#define MAXB     32
#define NT       256
#define TILE     32

__device__ float g_feat[MAXB * FEAT_DIM];

// ---------------- packed f32x2 helpers ----------------
__device__ __forceinline__ ull pack2(float lo, float hi) {
    ull r; asm("mov.b64 %0, {%1, %2};" : "=l"(r) : "f"(lo), "f"(hi)); return r;
}
__device__ __forceinline__ ull fma2(ull a, ull b, ull c) {
    ull r; asm("fma.rn.f32x2 %0, %1, %2, %3;" : "=l"(r) : "l"(a), "l"(b), "l"(c)); return r;
}
__device__ __forceinline__ ull mul2(ull a, ull b) {
    ull r; asm("mul.rn.f32x2 %0, %1, %2;" : "=l"(r) : "l"(a), "l"(b)); return r;
}
__device__ __forceinline__ ull add2(ull a, ull b) {
    ull r; asm("add.rn.f32x2 %0, %1, %2;" : "=l"(r) : "l"(a), "l"(b)); return r;
}

#define C06P 0x3F19999A3F19999AULL   // (0.6f, 0.6f)
#define C04P 0x3ECCCCCD3ECCCCCDULL   // (0.4f, 0.4f)
#define ONE2 0x3F8000003F800000ULL   // (1.0f, 1.0f)

// lrelu(v) = 0.6*v + 0.4*|v|   (exact: v>=0 -> v, v<0 -> 0.2v), branch-free packed
__device__ __forceinline__ ull lrelu2(ull v) {
    ull a = v & 0x7FFFFFFF7FFFFFFFULL;
    return fma2(a, (ull)C04P, mul2(v, (ull)C06P));
}

// ---------------- merged preamble: mean(thumb) + GEMV, one launch ----------------
#define FT 384
__global__ void feat_kernel(const float* __restrict__ thumb,
                            const float* __restrict__ Wm,
                            const float* __restrict__ bm, int HW) {
    int b = blockIdx.x;
    int tid = threadIdx.x;
    __shared__ float red[FT / 32][3];
    __shared__ float m[3];
    const float4* p = (const float4*)(thumb + (size_t)b * 3 * HW);
    int n4c = HW / 4;
    float s[3];
    #pragma unroll
    for (int c = 0; c < 3; c++) {
        float acc = 0.0f;
        for (int i = tid; i < n4c; i += FT) {
            float4 v = p[c * n4c + i];
            acc += (v.x + v.y) + (v.z + v.w);
        }
        s[c] = acc;
    }
    #pragma unroll
    for (int c = 0; c < 3; c++) {
        float v = s[c];
        #pragma unroll
        for (int o = 16; o > 0; o >>= 1) v += __shfl_down_sync(0xffffffffu, v, o);
        if ((tid & 31) == 0) red[tid >> 5][c] = v;
    }
    __syncthreads();
    if (tid == 0) {
        float inv = 1.0f / (float)HW;
        #pragma unroll
        for (int c = 0; c < 3; c++) {
            float t = 0.0f;
            #pragma unroll
            for (int w = 0; w < FT / 32; w++) t += red[w][c];
            m[c] = t * inv;
        }
    }
    __syncthreads();
    if (tid < FEAT_DIM) {
        g_feat[b * FEAT_DIM + tid] =
            m[0] * Wm[tid] + m[1] * Wm[FEAT_DIM + tid] + m[2] * Wm[2 * FEAT_DIM + tid]
            + bm[tid];
    }
}

// ---------------- one 3x3 conv layer on pixel pairs ----------------
// src (S x S x 3) -> dst (D x D x 3), D = S - 2. Work item = 2 adjacent pixels.
// Weights staged per (ic,ky): only 9 packed regs live -> low register pressure.
template <int S, int D, int SLOTS, bool STORE>
__device__ __forceinline__ void conv3_pairs(const float* __restrict__ src,
                                            float* __restrict__ dst,
                                            const ull* __restrict__ wPack,
                                            int tid, ull outReg[][3]) {
    constexpr int PW = D / 2;
    constexpr int NP = D * PW;
    int off[SLOTS];
    #pragma unroll
    for (int k = 0; k < SLOTS; k++) {
        int p = tid + k * NT;
        int y = p / PW, x = (p - y * PW) * 2;
        off[k] = y * S + x;
    }
    ull acc[SLOTS][3];
    #pragma unroll
    for (int oc = 0; oc < 3; oc++) {
        ull bb = wPack[81 + oc];
        #pragma unroll
        for (int k = 0; k < SLOTS; k++) acc[k][oc] = bb;
    }
    #pragma unroll
    for (int ic = 0; ic < 3; ic++) {
        #pragma unroll
        for (int ky = 0; ky < 3; ky++) {
            ull w00 = wPack[ 0 + ic * 9 + ky * 3 + 0];
            ull w01 = wPack[ 0 + ic * 9 + ky * 3 + 1];
            ull w02 = wPack[ 0 + ic * 9 + ky * 3 + 2];
            ull w10 = wPack[27 + ic * 9 + ky * 3 + 0];
            ull w11 = wPack[27 + ic * 9 + ky * 3 + 1];
            ull w12 = wPack[27 + ic * 9 + ky * 3 + 2];
            ull w20 = wPack[54 + ic * 9 + ky * 3 + 0];
            ull w21 = wPack[54 + ic * 9 + ky * 3 + 1];
            ull w22 = wPack[54 + ic * 9 + ky * 3 + 2];
            #pragma unroll
            for (int k = 0; k < SLOTS; k++) {
                bool active = ((k + 1) * NT <= NP) || (tid + k * NT < NP);
                if (active) {
                    const float* s = src + ic * S * S + ky * S + off[k];
                    float2 a = *(const float2*)s;
                    float2 b = *(const float2*)(s + 2);
                    ull v0 = pack2(a.x, a.y);
                    ull v1 = pack2(a.y, b.x);
                    ull v2 = pack2(b.x, b.y);
                    acc[k][0] = fma2(w00, v0, acc[k][0]);
                    acc[k][0] = fma2(w01, v1, acc[k][0]);
                    acc[k][0] = fma2(w02, v2, acc[k][0]);
                    acc[k][1] = fma2(w10, v0, acc[k][1]);
                    acc[k][1] = fma2(w11, v1, acc[k][1]);
                    acc[k][1] = fma2(w12, v2, acc[k][1]);
                    acc[k][2] = fma2(w20, v0, acc[k][2]);
                    acc[k][2] = fma2(w21, v1, acc[k][2]);
                    acc[k][2] = fma2(w22, v2, acc[k][2]);
                }
            }
        }
    }
    #pragma unroll
    for (int k = 0; k < SLOTS; k++) {
        int p = tid + k * NT;
        bool active = ((k + 1) * NT <= NP) || (p < NP);
        if (active) {
            int y = p / PW, x = (p - y * PW) * 2;
            #pragma unroll
            for (int oc = 0; oc < 3; oc++) {
                ull r = lrelu2(acc[k][oc]);
                if (STORE) *(ull*)(dst + oc * D * D + y * D + x) = r;
                else       outReg[k][oc] = r;
            }
        }
    }
}

// ---------------- fused conv stack + attention (main + thumb merged) ----------------
__global__ __launch_bounds__(NT, 3) void conv_att_kernel(
    const float* __restrict__ xMain, const float* __restrict__ xThumb,
    float* __restrict__ outAll, int Hm, int B, int tRowM) {
    __shared__ __align__(16) float bufA[3 * 38 * 38];
    __shared__ __align__(16) float bufB[3 * 36 * 36];
    __shared__ ull sPack[FEAT_DIM];

    int mainTotal = B * tRowM * tRowM;
    int bid = blockIdx.x;
    const float* src; float* dst;
    int H, tRow, b, tile;
    if (bid < mainTotal) {
        int per = tRowM * tRowM;
        b = bid / per; tile = bid - b * per;
        H = Hm; tRow = tRowM;
        src = xMain + (size_t)b * 3 * H * H;
        dst = outAll + (size_t)b * 3 * H * H;
    } else {
        int r = bid - mainTotal;
        b = r >> 2; tile = r & 3;
        H = 64; tRow = 2;
        src = xThumb + (size_t)b * 3 * 64 * 64;
        dst = outAll + (size_t)B * 3 * Hm * Hm + (size_t)b * 3 * 64 * 64;
    }
    int ty = tile / tRow, tx = tile - ty * tRow;
    int y0 = ty * TILE, x0 = tx * TILE;
    int tid = threadIdx.x;

    // splat features into packed SMEM table
    for (int j = tid; j < FEAT_DIM; j += NT) {
        float f = g_feat[b * FEAT_DIM + j];
        sPack[j] = pack2(f, f);
    }

    // load input tile with halo 3 (zero-padded at borders)
    for (int i = tid; i < 3 * 38 * 38; i += NT) {
        int c = i / (38 * 38);
        int r = i - c * (38 * 38);
        int y = r / 38, xx = r - y * 38;
        int gy = y0 - 3 + y, gx = x0 - 3 + xx;
        float v = 0.0f;
        if (gy >= 0 && gy < H && gx >= 0 && gx < H)
            v = __ldg(&src[((size_t)c * H + gy) * H + gx]);
        bufA[i] = v;
    }
    __syncthreads();

    // L1: bufA(38) -> bufB(36)
    conv3_pairs<38, 36, 3, true>(bufA, bufB, sPack, tid, (ull(*)[3])nullptr);

    // stash residual pairs (input tile center) before bufA is reused
    ull resP[2][3];
    #pragma unroll
    for (int k = 0; k < 2; k++) {
        int p = tid + k * NT;
        int y = p >> 4, x = (p & 15) * 2;
        #pragma unroll
        for (int oc = 0; oc < 3; oc++) {
            const float* q = &bufA[(oc * 38 + 3 + y) * 38 + 3 + x];
            resP[k][oc] = pack2(q[0], q[1]);
        }
    }
    __syncthreads();

    // L2: bufB(36) -> bufA(34)
    conv3_pairs<36, 34, 3, true>(bufB, bufA, sPack + 84, tid, (ull(*)[3])nullptr);
    __syncthreads();

    // L3: bufA(34) -> registers (2 pair-slots/thread, exactly 32x32 tile)
    ull cur[2][3];
    conv3_pairs<34, 32, 2, false>(bufA, (float*)nullptr, sPack + 168, tid, cur);

    // 5x conv1x1 (packed, in registers)
    #pragma unroll
    for (int l = 0; l < 5; l++) {
        const ull* wl = sPack + 252 + l * 12;
        ull W0 = wl[0], W1 = wl[1], W2 = wl[2];
        ull W3 = wl[3], W4 = wl[4], W5 = wl[5];
        ull W6 = wl[6], W7 = wl[7], W8 = wl[8];
        ull B0 = wl[9], B1 = wl[10], B2 = wl[11];
        #pragma unroll
        for (int k = 0; k < 2; k++) {
            ull c0 = cur[k][0], c1 = cur[k][1], c2 = cur[k][2];
            ull n0 = fma2(W0, c0, fma2(W1, c1, fma2(W2, c2, B0)));
            ull n1 = fma2(W3, c0, fma2(W4, c1, fma2(W5, c2, B1)));
            ull n2 = fma2(W6, c0, fma2(W7, c1, fma2(W8, c2, B2)));
            cur[k][0] = lrelu2(n0);
            cur[k][1] = lrelu2(n1);
            cur[k][2] = lrelu2(n2);
        }
    }
    // residual add
    #pragma unroll
    for (int k = 0; k < 2; k++)
        #pragma unroll
        for (int oc = 0; oc < 3; oc++)
            cur[k][oc] = add2(resP[k][oc], cur[k][oc]);

    // polynomial attention + store (packed, 2 pixels per store)
    float invH = 1.0f / (float)H;
    #pragma unroll
    for (int k = 0; k < 2; k++) {
        int p = tid + k * NT;
        int y = p >> 4, x = (p & 15) * 2;
        int gy = y0 + y, gx = x0 + x;
        float hv = (float)gy * invH;
        ull hP = pack2(hv, hv);
        ull wP = pack2((float)gx * invH, (float)(gx + 1) * invH);
        #pragma unroll
        for (int oc = 0; oc < 3; oc++) {
            ull v = cur[k][oc];
            ull att = (ull)ONE2;
            #pragma unroll
            for (int i = 0; i < 4; i++) {
                const ull* f = sPack + 312 + oc * 16 + i * 4;
                ull t = fma2(f[0], hP, fma2(f[1], wP, fma2(f[2], v, f[3])));
                att = mul2(att, t);
            }
            ull r = mul2(v, add2((ull)ONE2, att));
            *(ull*)&dst[((size_t)oc * H + gy) * H + gx] = r;
        }
    }
}

// ---------------- launch ----------------
extern "C" void kernel_launch(void* const* d_in, const int* in_sizes, int n_in,
                              void* d_out, int out_size) {
    const float* x     = (const float*)d_in[0];
    const float* thumb = (const float*)d_in[1];
    const float* Wm    = (const float*)d_in[2];
    const float* bm    = (const float*)d_in[3];
    float* out = (float*)d_out;

    int Ht = 64;
    int B  = in_sizes[1] / (3 * Ht * Ht);
    if (B < 1) B = 1;
    if (B > MAXB) B = MAXB;
    int hw = in_sizes[0] / (3 * B);
    int Hm = (int)(sqrt((double)hw) + 0.5);

    feat_kernel<<<B, FT>>>(thumb, Wm, bm, Ht * Ht);

    int tRowM = Hm / TILE;
    int total = B * tRowM * tRowM + B * 4;  // main tiles + thumb tiles
    conv_att_kernel<<<total, NT>>>(x, thumb, out, Hm, B, tRowM);
}